// round 1
// baseline (speedup 1.0000x reference)
#include <cuda_runtime.h>

// Problem constants
#define B        8
#define IN_CH    64
#define OUT_CH   64
#define GROUPS   8
#define FPG      8          // channels per group
#define KS       3
#define H        256
#define W        256
#define PLANE    (H * W)    // 65536
#define REP_DIM  32
#define K9_PER_B (OUT_CH * KS * KS)   // 576

#define TILE     64
#define HALO     (TILE + 2)  // 66
#define THREADS  256

// Scratch for the dynamic kernels: [B][OUT_CH][9]
__device__ float g_k9[B * K9_PER_B];

// ---------------------------------------------------------------------------
// Kernel 1: k9 = leaky_relu(rep @ W^T, 0.1)
//   rep: [B, 32], W: [576, 32] (torch Linear layout), out: [B, 576]
// ---------------------------------------------------------------------------
__global__ void compute_k9_kernel(const float* __restrict__ rep,
                                  const float* __restrict__ Wm) {
    int j = blockIdx.x * blockDim.x + threadIdx.x;
    if (j >= B * K9_PER_B) return;
    int b = j / K9_PER_B;
    int f = j - b * K9_PER_B;
    const float* r = rep + b * REP_DIM;
    const float* w = Wm + f * REP_DIM;
    float s = 0.f;
#pragma unroll
    for (int i = 0; i < REP_DIM; i++) s = fmaf(r[i], w[i], s);
    g_k9[j] = (s > 0.f) ? s : 0.1f * s;
}

// ---------------------------------------------------------------------------
// Kernel 2: fused group-sum + per-channel 3x3 stencil with reflect padding.
// grid: (16 tiles, GROUPS, B), block: 256 threads, tile 64x64.
// ---------------------------------------------------------------------------
__device__ __forceinline__ int reflect_idx(int i) {
    // pad=1 reflect: -1 -> 1, 256 -> 254
    i = (i < 0) ? -i : i;
    return (i > H - 1) ? (2 * (H - 1) - i) : i;
}

__global__ __launch_bounds__(THREADS, 2)
void dyn_conv_kernel(const float* __restrict__ x,
                     float* __restrict__ out) {
    const int b = blockIdx.z;
    const int g = blockIdx.y;
    const int ty = (blockIdx.x >> 2) * TILE;   // 4x4 tiles over 256x256
    const int tx = (blockIdx.x & 3) * TILE;
    const int tid = threadIdx.x;

    __shared__ float S[HALO * HALO];   // group-sum tile with 1-px halo
    __shared__ float k9s[FPG * 9];     // 8 out-channels x 9 taps

    // Load this (b, g)'s 72 dynamic weights
    if (tid < FPG * 9) {
        k9s[tid] = g_k9[b * K9_PER_B + (g * FPG) * 9 + tid];
    }

    // Build S: sum of the 8 input channels of this group, reflect-padded halo
    const float* xbase = x + ((size_t)(b * IN_CH + g * FPG)) * PLANE;
    for (int i = tid; i < HALO * HALO; i += THREADS) {
        int ly = i / HALO;
        int lx = i - ly * HALO;
        int gy = reflect_idx(ty + ly - 1);
        int gx = reflect_idx(tx + lx - 1);
        const float* p = xbase + gy * W + gx;
        float s = 0.f;
#pragma unroll
        for (int c = 0; c < FPG; c++) s += p[c * PLANE];
        S[i] = s;
    }
    __syncthreads();

    // Hoist k9 into registers (72 regs) — avoids 72 LDS per output position
    float kr[FPG * 9];
#pragma unroll
    for (int i = 0; i < FPG * 9; i++) kr[i] = k9s[i];

    // Each thread: one x-column, strip of 16 consecutive rows.
    const int lx = tid & 63;          // 0..63  (output x within tile)
    const int strip = tid >> 6;       // 0..3
    const int y0 = strip * 16;

    // Sliding window over S rows: a = row y, bb = row y+1, cc = row y+2
    float a0, a1, a2, b0, b1, b2, c0, c1, c2;
    {
        const float* Sr = &S[y0 * HALO + lx];
        a0 = Sr[0]; a1 = Sr[1]; a2 = Sr[2];
        Sr += HALO;
        b0 = Sr[0]; b1 = Sr[1]; b2 = Sr[2];
    }

    float* op = out + ((size_t)(b * OUT_CH + g * FPG)) * PLANE
                    + (ty + y0) * W + tx + lx;

#pragma unroll 4
    for (int y = y0; y < y0 + 16; y++) {
        const float* Sr = &S[(y + 2) * HALO + lx];
        c0 = Sr[0]; c1 = Sr[1]; c2 = Sr[2];

#pragma unroll
        for (int o = 0; o < FPG; o++) {
            float v;
            v = kr[o * 9 + 0] * a0;
            v = fmaf(kr[o * 9 + 1], a1, v);
            v = fmaf(kr[o * 9 + 2], a2, v);
            v = fmaf(kr[o * 9 + 3], b0, v);
            v = fmaf(kr[o * 9 + 4], b1, v);
            v = fmaf(kr[o * 9 + 5], b2, v);
            v = fmaf(kr[o * 9 + 6], c0, v);
            v = fmaf(kr[o * 9 + 7], c1, v);
            v = fmaf(kr[o * 9 + 8], c2, v);
            op[o * PLANE] = v;
        }
        op += W;
        a0 = b0; a1 = b1; a2 = b2;
        b0 = c0; b1 = c1; b2 = c2;
    }
}

// ---------------------------------------------------------------------------
// Launch
// ---------------------------------------------------------------------------
extern "C" void kernel_launch(void* const* d_in, const int* in_sizes, int n_in,
                              void* d_out, int out_size) {
    const float* x   = (const float*)d_in[0];   // [8, 64, 256, 256]
    const float* rep = (const float*)d_in[1];   // [8, 32]
    const float* Wm  = (const float*)d_in[2];   // [576, 32]
    float* out = (float*)d_out;                 // [8, 64, 256, 256]

    (void)in_sizes; (void)n_in; (void)out_size;

    compute_k9_kernel<<<(B * K9_PER_B + 255) / 256, 256>>>(rep, Wm);

    dim3 grid(16, GROUPS, B);   // 4x4 tiles, 8 groups, 8 batches
    dyn_conv_kernel<<<grid, THREADS>>>(x, out);
}

// round 3
// speedup vs baseline: 1.3323x; 1.3323x over previous
#include <cuda_runtime.h>

// Problem constants
#define B        8
#define IN_CH    64
#define OUT_CH   64
#define GROUPS   8
#define FPG      8
#define H        256
#define W        256
#define PLANE    (H * W)
#define REP_DIM  32
#define K9_PER_B (OUT_CH * 9)   // 576

#define TILE     64
#define HALO     66
#define SSTRIDE  68             // padded row stride (float2 alignment, even)
#define THREADS  256

// Dynamic per-sample kernels: [B][OUT_CH][9]
__device__ float g_k9[B * K9_PER_B];

// ---------------------------------------------------------------------------
// Kernel 1: k9 = leaky_relu(rep @ W^T, 0.1)
// ---------------------------------------------------------------------------
__global__ void compute_k9_kernel(const float* __restrict__ rep,
                                  const float* __restrict__ Wm) {
    int j = blockIdx.x * blockDim.x + threadIdx.x;
    if (j >= B * K9_PER_B) return;
    int b = j / K9_PER_B;
    int f = j - b * K9_PER_B;
    const float* r = rep + b * REP_DIM;
    const float* w = Wm + f * REP_DIM;
    float s = 0.f;
#pragma unroll
    for (int i = 0; i < REP_DIM; i++) s = fmaf(r[i], w[i], s);
    g_k9[j] = (s > 0.f) ? s : 0.1f * s;
}

// ---------------------------------------------------------------------------
// Kernel 2: fused group-sum + per-channel 3x3 stencil, reflect padding.
// grid: (16 tiles, GROUPS, B), 256 threads, 64x64 tile.
// Thread layout: 32 x-pairs x 4 row-strips(16) x 2 channel-halves(4 ch).
// ---------------------------------------------------------------------------
__device__ __forceinline__ int reflect_idx(int i) {
    i = (i < 0) ? -i : i;
    return (i > H - 1) ? (2 * (H - 1) - i) : i;
}

__global__ __launch_bounds__(THREADS, 3)
void dyn_conv_kernel(const float* __restrict__ x,
                     float* __restrict__ out) {
    const int b = blockIdx.z;
    const int g = blockIdx.y;
    const int ty = (blockIdx.x >> 2) * TILE;
    const int tx = (blockIdx.x & 3) * TILE;
    const int tid = threadIdx.x;

    __shared__ float S[SSTRIDE * HALO];  // group-sum tile + halo (padded stride)
    __shared__ float k9s[FPG * 9];

    if (tid < FPG * 9) {
        k9s[tid] = g_k9[b * K9_PER_B + (g * FPG) * 9 + tid];
    }

    // Build S = sum of 8 input channels of this group (reflect-padded halo).
    const float* xbase = x + ((size_t)(b * IN_CH + g * FPG)) * PLANE;
#pragma unroll 2
    for (int i = tid; i < HALO * HALO; i += THREADS) {
        int ly = i / HALO;
        int lx = i - ly * HALO;
        int gy = reflect_idx(ty + ly - 1);
        int gx = reflect_idx(tx + lx - 1);
        const float* p = xbase + gy * W + gx;
        float s = 0.f;
#pragma unroll
        for (int c = 0; c < FPG; c++) s += p[c * PLANE];
        S[ly * SSTRIDE + lx] = s;
    }
    __syncthreads();

    // Thread coordinates
    const int xp    = tid & 31;          // x-pair index 0..31
    const int strip = (tid >> 5) & 3;    // 0..3, 16 rows each
    const int co0   = (tid >> 7) * 4;    // channel half: 0 or 4
    const int lx0   = xp * 2;            // output x within tile (even)
    const int y0    = strip * 16;

    // 36 dynamic weights in registers
    float kr[36];
#pragma unroll
    for (int c = 0; c < 4; c++)
#pragma unroll
        for (int t = 0; t < 9; t++)
            kr[c * 9 + t] = k9s[(co0 + c) * 9 + t];

    // Sliding 3-row window of 4 S values each (columns lx0..lx0+3)
    float a0, a1, a2, a3;   // row y
    float b0, b1, b2, b3;   // row y+1
    float d0, d1, d2, d3;   // row y+2
    {
        const float* Sr = &S[y0 * SSTRIDE + lx0];
        float2 u = *(const float2*)(Sr);
        float2 v = *(const float2*)(Sr + 2);
        a0 = u.x; a1 = u.y; a2 = v.x; a3 = v.y;
        Sr += SSTRIDE;
        u = *(const float2*)(Sr);
        v = *(const float2*)(Sr + 2);
        b0 = u.x; b1 = u.y; b2 = v.x; b3 = v.y;
    }

    float* op = out + ((size_t)(b * OUT_CH + g * FPG + co0)) * PLANE
                    + (ty + y0) * W + tx + lx0;

#pragma unroll 4
    for (int y = 0; y < 16; y++) {
        const float* Sr = &S[(y0 + y + 2) * SSTRIDE + lx0];
        float2 u = *(const float2*)(Sr);
        float2 v = *(const float2*)(Sr + 2);
        d0 = u.x; d1 = u.y; d2 = v.x; d3 = v.y;

#pragma unroll
        for (int ch = 0; ch < 4; ch++) {
            const float* k = &kr[ch * 9];
            float v0 = k[0] * a0;
            float v1 = k[0] * a1;
            v0 = fmaf(k[1], a1, v0);  v1 = fmaf(k[1], a2, v1);
            v0 = fmaf(k[2], a2, v0);  v1 = fmaf(k[2], a3, v1);
            v0 = fmaf(k[3], b0, v0);  v1 = fmaf(k[3], b1, v1);
            v0 = fmaf(k[4], b1, v0);  v1 = fmaf(k[4], b2, v1);
            v0 = fmaf(k[5], b2, v0);  v1 = fmaf(k[5], b3, v1);
            v0 = fmaf(k[6], d0, v0);  v1 = fmaf(k[6], d1, v1);
            v0 = fmaf(k[7], d1, v0);  v1 = fmaf(k[7], d2, v1);
            v0 = fmaf(k[8], d2, v0);  v1 = fmaf(k[8], d3, v1);
            __stcs((float2*)(op + ch * PLANE), make_float2(v0, v1));
        }
        op += W;
        a0 = b0; a1 = b1; a2 = b2; a3 = b3;
        b0 = d0; b1 = d1; b2 = d2; b3 = d3;
    }
}

// ---------------------------------------------------------------------------
// Launch
// ---------------------------------------------------------------------------
extern "C" void kernel_launch(void* const* d_in, const int* in_sizes, int n_in,
                              void* d_out, int out_size) {
    const float* x   = (const float*)d_in[0];   // [8, 64, 256, 256]
    const float* rep = (const float*)d_in[1];   // [8, 32]
    const float* Wm  = (const float*)d_in[2];   // [576, 32]
    float* out = (float*)d_out;                 // [8, 64, 256, 256]

    (void)in_sizes; (void)n_in; (void)out_size;

    compute_k9_kernel<<<(B * K9_PER_B + 255) / 256, 256>>>(rep, Wm);

    dim3 grid(16, GROUPS, B);
    dyn_conv_kernel<<<grid, THREADS>>>(x, out);
}